// round 3
// baseline (speedup 1.0000x reference)
#include <cuda_runtime.h>

// PairmixLayer: out[n,f,l3^2+c] = sum_{l1,l2} (sum_{a,b} x[n,f,l1^2+a] y[n,f,l2^2+b] cg[l1,l2,l3,a,b,c])
//                                 * (sum_k W[idx(l1,l2,l3)][f][k] g[n,k])
// N=150000, F=64, K=16, L=2. One thread computes TWO n's (same f) with packed
// f32x2 math (FFMA2) to double fp32 FMA throughput.

#define NF   64
#define KK   16
#define NIDX 27
#define NCG  3375   // 3*3*3*5*5*5
#define TPB  128

typedef unsigned long long u64;

// Transposed weights scratch: Wt[idx][k][f]  (coalesced over f for lanes)
__device__ float d_Wt[NIDX * KK * NF];

__device__ __forceinline__ u64 pk2(float lo, float hi) {
    u64 r; asm("mov.b64 %0, {%1,%2};" : "=l"(r) : "f"(lo), "f"(hi)); return r;
}
__device__ __forceinline__ void unpk2(u64 v, float& a, float& b) {
    asm("mov.b64 {%0,%1}, %2;" : "=f"(a), "=f"(b) : "l"(v));
}
__device__ __forceinline__ u64 rep2(float x) {
    u64 r; asm("mov.b64 %0, {%1,%1};" : "=l"(r) : "f"(x)); return r;
}
__device__ __forceinline__ u64 fma2(u64 a, u64 b, u64 c) {
    u64 r; asm("fma.rn.f32x2 %0, %1, %2, %3;" : "=l"(r) : "l"(a), "l"(b), "l"(c)); return r;
}
__device__ __forceinline__ u64 mul2(u64 a, u64 b) {
    u64 r; asm("mul.rn.f32x2 %0, %1, %2;" : "=l"(r) : "l"(a), "l"(b)); return r;
}

// ---------------------------------------------------------------------------
// Kernel 1: transpose weights (27,64,16) -> Wt (27,16,64)
// ---------------------------------------------------------------------------
__global__ void transpose_w_kernel(const float* __restrict__ W) {
    int i = blockIdx.x * blockDim.x + threadIdx.x;
    if (i < NIDX * NF * KK) {
        int idx = i / (NF * KK);
        int rem = i % (NF * KK);
        int f = rem / KK;
        int k = rem % KK;
        d_Wt[(idx * KK + k) * NF + f] = W[i];
    }
}

// ---------------------------------------------------------------------------
// Kernel 2: main. One thread = one n-pair (n0=2p, n1=2p+1) for one f.
// Warp = 32 consecutive f of one pair -> x/y/w loads coalesced.
// ---------------------------------------------------------------------------
__global__ __launch_bounds__(TPB)
void pairmix_kernel(const float* __restrict__ x,
                    const float* __restrict__ y,
                    const float* __restrict__ r,
                    const float* __restrict__ cgc,
                    float* __restrict__ out,
                    int N) {
    // cgc staged in shared, pre-replicated into f32x2 pairs (broadcast LDS.64)
    __shared__ u64 s_cg[NCG];
    for (int i = threadIdx.x; i < NCG; i += TPB) s_cg[i] = rep2(cgc[i]);
    __syncthreads();

    long long t = (long long)blockIdx.x * TPB + threadIdx.x;
    int f = (int)(t & 63);
    long long pair = t >> 6;
    long long npairs = ((long long)N + 1) >> 1;
    if (pair >= npairs) return;

    int n0 = (int)(pair * 2);
    int n1 = n0 + 1;
    bool has1 = (n1 < N);
    if (!has1) n1 = n0;

    // ---- load x,y rows for both n's, pack over the pair ----
    const float* px0 = x + ((long long)n0 * NF + f) * 9;
    const float* px1 = x + ((long long)n1 * NF + f) * 9;
    const float* py0 = y + ((long long)n0 * NF + f) * 9;
    const float* py1 = y + ((long long)n1 * NF + f) * 9;
    u64 xp[9], yp[9];
#pragma unroll
    for (int a = 0; a < 9; a++) {
        xp[a] = pk2(px0[a], px1[a]);
        yp[a] = pk2(py0[a], py1[a]);
    }

    // ---- Bernstein basis g[k] = C(15,k) u^k (1-u)^(15-k), packed over pair ----
    float r0 = r[n0], r1 = r[n1];
    float u0 = fminf(fmaxf(r0 * 0.2f, 0.0f), 1.0f);
    float u1 = fminf(fmaxf(r1 * 0.2f, 0.0f), 1.0f);
    u64 uu = pk2(u0, u1);
    u64 vv = pk2(1.0f - u0, 1.0f - u1);
    const float binom[KK] = {1.f, 15.f, 105.f, 455.f, 1365.f, 3003.f, 5005.f, 6435.f,
                             6435.f, 5005.f, 3003.f, 1365.f, 455.f, 105.f, 15.f, 1.f};
    u64 gp[KK];
    {
        u64 pu[KK], pv[KK];
        pu[0] = rep2(1.0f);
        pv[0] = rep2(1.0f);
#pragma unroll
        for (int k = 1; k < KK; k++) {
            pu[k] = mul2(pu[k - 1], uu);
            pv[k] = mul2(pv[k - 1], vv);
        }
#pragma unroll
        for (int k = 0; k < KK; k++)
            gp[k] = mul2(mul2(pu[k], pv[(KK - 1) - k]), rep2(binom[k]));
    }

    // ---- main contraction; radial mix computed in-loop (low reg pressure) ----
    u64 outp[9];
#pragma unroll
    for (int c = 0; c < 9; c++) outp[c] = rep2(0.0f);

#pragma unroll
    for (int l1 = 0; l1 < 3; l1++) {
#pragma unroll
        for (int l2 = 0; l2 < 3; l2++) {
            const int d1 = 2 * l1 + 1;
            const int d2 = 2 * l2 + 1;
            const int idx0 = l1 * 9 + l2 * 3;  // idx for l3=0

            // radial mixing for the 3 l3's of this (l1,l2):
            // mul[l3] = sum_k Wt[idx0+l3][k][f] * g[k]
            u64 ml[3];
#pragma unroll
            for (int l3 = 0; l3 < 3; l3++) {
                const float* w = d_Wt + ((idx0 + l3) * KK) * NF + f;
                u64 acc = rep2(0.0f);
#pragma unroll
                for (int k = 0; k < KK; k++)
                    acc = fma2(rep2(w[k * NF]), gp[k], acc);
                ml[l3] = acc;
            }

            // outer products p[a][b] = x_a * y_b (packed over the pair)
            u64 p[5][5];
#pragma unroll
            for (int a = 0; a < d1; a++)
#pragma unroll
                for (int b = 0; b < d2; b++)
                    p[a][b] = mul2(xp[l1 * l1 + a], yp[l2 * l2 + b]);

#pragma unroll
            for (int l3 = 0; l3 < 3; l3++) {
                const int d3 = 2 * l3 + 1;
                const int cgbase = (idx0 + l3) * 125;
#pragma unroll
                for (int c = 0; c < d3; c++) {
                    u64 T = rep2(0.0f);
#pragma unroll
                    for (int a = 0; a < d1; a++)
#pragma unroll
                        for (int b = 0; b < d2; b++)
                            T = fma2(p[a][b], s_cg[cgbase + a * 25 + b * 5 + c], T);
                    outp[l3 * l3 + c] = fma2(T, ml[l3], outp[l3 * l3 + c]);
                }
            }
        }
    }

    // ---- store ----
    float* o0 = out + ((long long)n0 * NF + f) * 9;
    float* o1 = out + ((long long)n1 * NF + f) * 9;
#pragma unroll
    for (int c = 0; c < 9; c++) {
        float a, b;
        unpk2(outp[c], a, b);
        o0[c] = a;
        if (has1) o1[c] = b;
    }
}

// ---------------------------------------------------------------------------
extern "C" void kernel_launch(void* const* d_in, const int* in_sizes, int n_in,
                              void* d_out, int out_size) {
    const float* x = (const float*)d_in[0];
    const float* y = (const float*)d_in[1];
    const float* r = (const float*)d_in[2];
    const float* weights = (const float*)d_in[3];
    const float* cgc = (const float*)d_in[4];
    float* out = (float*)d_out;

    int N = in_sizes[2];  // r has N elements

    // 1) transpose weights into d_Wt
    int wtot = NIDX * NF * KK;
    transpose_w_kernel<<<(wtot + 255) / 256, 256>>>(weights);

    // 2) main kernel: one thread per (n-pair, f)
    long long npairs = ((long long)N + 1) >> 1;
    long long nthreads = npairs * NF;
    int blocks = (int)((nthreads + TPB - 1) / TPB);
    pairmix_kernel<<<blocks, TPB>>>(x, y, r, cgc, out, N);
}